// round 15
// baseline (speedup 1.0000x reference)
#include <cuda_runtime.h>
#include <cuda_fp16.h>

#define NB 2048
#define NT 128
#define NS 256
#define NH 64
#define NE 32
#define NV 29

// ---------------- precomputed constants (filled by setup_kernel) ----------------
// thread t (0..127): hh = t>>1, c = t&1; gate columns j0 = hh + 64c, j1 = 128 + hh + 64c.
// (even lane: i_hh and g_hh; odd lane: f_hh and o_hh)
__device__ __half2 g_wTh[128 * 128];  // [k][t] = half2(W[k][j0], W[k][j1]); k<64: W_ih ctx, k>=64: W_hh
__device__ float2  g_lut2[NV * 128];  // [v][t] = (lut[v][j0], lut[v][j1])
__device__ float   g_fcP[128 * 32];   // [k][v]: xc order [context(0..63), h_new(64..127)]; v>=29 -> 0
__device__ float   g_fcb[32];

__device__ __forceinline__ float sigf(float x) {
    return __fdividef(1.0f, 1.0f + __expf(-x));
}
__device__ __forceinline__ float tanhfast(float x) {
    return 1.0f - __fdividef(2.0f, __expf(2.0f * x) + 1.0f);
}

__global__ void setup_kernel(const float* __restrict__ emb, const float* __restrict__ W_ih,
                             const float* __restrict__ W_hh, const float* __restrict__ b_ih,
                             const float* __restrict__ b_hh, const float* __restrict__ fc_W,
                             const float* __restrict__ fc_b) {
    const int t = threadIdx.x;     // 0..127
    const int blk = blockIdx.x;
    const int hh = t >> 1, c = t & 1;
    const int j0 = hh + 64 * c;
    const int j1 = 128 + hh + 64 * c;
    if (blk < NV) {
        float s[2];
        const int js[2] = { j0, j1 };
#pragma unroll
        for (int q = 0; q < 2; q++) {
            const int j = js[q];
            float acc = b_ih[j] + b_hh[j];
#pragma unroll
            for (int e = 0; e < NE; e++) acc += emb[blk * NE + e] * W_ih[j * (NE + NH) + e];
            s[q] = acc;
        }
        g_lut2[blk * 128 + t] = make_float2(s[0], s[1]);
    } else if (blk == NV) {
        for (int k = 0; k < 128; k++) {
            float w0, w1;
            if (k < 64) {
                w0 = W_ih[j0 * (NE + NH) + NE + k];
                w1 = W_ih[j1 * (NE + NH) + NE + k];
            } else {
                w0 = W_hh[j0 * NH + (k - 64)];
                w1 = W_hh[j1 * NH + (k - 64)];
            }
            g_wTh[k * 128 + t] = __floats2half2_rn(w0, w1);
        }
    } else {
        for (int idx = t; idx < 4096; idx += 128) {
            const int k = idx >> 5, v = idx & 31;
            float val = 0.0f;
            if (v < NV) val = (k < 64) ? fc_W[v * 128 + 64 + k] : fc_W[v * 128 + (k - 64)];
            g_fcP[idx] = val;
        }
        if (t < 32) g_fcb[t] = (t < NV) ? fc_b[t] : 0.0f;
    }
}

// ---------------- smem layout (offsets in floats), 1 row per CTA, 128 threads ----------------
#define OFF_ENC16  0        // 256*72 halves = 9216 floats
#define OFF_FCP    9216     // 4096
#define OFF_CTX    13312    // 64
#define OFF_HBUF   13376    // 2 * 64 (h ping-pong)
#define OFF_CST    13504    // 64
#define OFF_E      13568    // 256  softmax weights (warp-private)
#define OFF_CPART  13824    // 256
#define OFF_LPART  14080    // 128
#define OFF_WSUM   14208    // 8 (4 used)
#define OFF_FCB    14216    // 32
#define OFF_Y      14248    // 128 ints
#define SMEM_FLOATS 14376
#define SMEM_BYTES (SMEM_FLOATS * 4)   // 57504 -> 2 CTAs/SM = 115 KB

__global__ void __launch_bounds__(128, 2)
decoder_kernel(const int* __restrict__ y, const float* __restrict__ h0,
               const float* __restrict__ c0, const float* __restrict__ enc,
               float* __restrict__ out) {
    extern __shared__ float sm[];
    __half*  sEnc16 = (__half*)(sm + OFF_ENC16);
    float*   sFcP   = sm + OFF_FCP;
    float*   sCtx   = sm + OFF_CTX;
    float*   sHbuf  = sm + OFF_HBUF;
    float*   sCst   = sm + OFF_CST;
    float*   sE     = sm + OFF_E;
    float*   sCpart = sm + OFF_CPART;
    float*   sLpart = sm + OFF_LPART;
    float*   sWsum  = sm + OFF_WSUM;
    float*   sFcb   = sm + OFF_FCB;
    int*     sY     = (int*)(sm + OFF_Y);

    const int b = blockIdx.x, tid = threadIdx.x;   // 128 threads
    const int lane = tid & 31, warp = tid >> 5;    // 4 warps

    // one-time loads
    const float* encb = enc + (size_t)b * (NS * NH);
    for (int idx = tid; idx < NS * NH; idx += 128) {
        const int s = idx >> 6, h = idx & 63;
        sEnc16[s * 72 + h] = __float2half(encb[idx]);
    }
    for (int idx = tid; idx < 4096; idx += 128) sFcP[idx] = g_fcP[idx];
    if (tid < 64) { sHbuf[tid] = h0[b * 64 + tid]; sCst[tid] = c0[b * 64 + tid]; }
    sY[tid] = y[b * 128 + tid];
    if (tid < 32) sFcb[tid] = g_fcb[tid];

    // per-thread packed gate weights for columns (j0, j1)
    __half2 w2[128];
#pragma unroll
    for (int k = 0; k < 128; k++) w2[k] = g_wTh[k * 128 + tid];
    __syncthreads();

    // scores: thread owns encoder rows s = tid and s = tid+128
    const uint4* er0 = (const uint4*)(sEnc16 + tid * 72);
    const uint4* er1 = er0 + 1152;                 // +128 rows * 72 halves
    // context: warp w <-> s blocks [32w,32w+32) and [128+32w,...), lane <-> h-pair
    const __half2* e2p  = (const __half2*)sEnc16 + warp * (32 * 36) + lane;
    const __half2* e2pB = e2p + 128 * 36;
    const float4*  ev4  = (const float4*)(sE + (warp << 5));
    const float4*  ev4B = (const float4*)(sE + 128 + (warp << 5));
    const int hh = tid >> 1;

    for (int t = 0; t < NT; t++) {
        const float* hP = sHbuf + (t & 1) * 64;        // h for this step
        float*       hN = sHbuf + ((t + 1) & 1) * 64;  // h_new written here
        const float2 lg = g_lut2[sY[t] * 128 + tid];   // L2 load; consumed in phase 4

        // ---- phase 1: fp16 scores (2 rows) + exp + gates_h (both cols) ----
        const float4* hv4 = (const float4*)hP;
        float a0 = 0.f, a1 = 0.f, a2 = 0.f, a3 = 0.f;
        float b0 = 0.f, b1 = 0.f, b2 = 0.f, b3 = 0.f;
        float g00 = 0.f, g01 = 0.f, g10 = 0.f, g11 = 0.f;
#pragma unroll
        for (int i = 0; i < 8; i++) {
            const uint4 u0 = er0[i];
            const uint4 u1 = er1[i];
            const float4 ha = hv4[2 * i], hb = hv4[2 * i + 1];
            float2 e;
            e = __half22float2(*(const __half2*)&u0.x); a0 = fmaf(e.x, ha.x, a0); a1 = fmaf(e.y, ha.y, a1);
            e = __half22float2(*(const __half2*)&u0.y); a2 = fmaf(e.x, ha.z, a2); a3 = fmaf(e.y, ha.w, a3);
            e = __half22float2(*(const __half2*)&u0.z); a0 = fmaf(e.x, hb.x, a0); a1 = fmaf(e.y, hb.y, a1);
            e = __half22float2(*(const __half2*)&u0.w); a2 = fmaf(e.x, hb.z, a2); a3 = fmaf(e.y, hb.w, a3);
            e = __half22float2(*(const __half2*)&u1.x); b0 = fmaf(e.x, ha.x, b0); b1 = fmaf(e.y, ha.y, b1);
            e = __half22float2(*(const __half2*)&u1.y); b2 = fmaf(e.x, ha.z, b2); b3 = fmaf(e.y, ha.w, b3);
            e = __half22float2(*(const __half2*)&u1.z); b0 = fmaf(e.x, hb.x, b0); b1 = fmaf(e.y, hb.y, b1);
            e = __half22float2(*(const __half2*)&u1.w); b2 = fmaf(e.x, hb.z, b2); b3 = fmaf(e.y, hb.w, b3);
            float2 wv;
            wv = __half22float2(w2[64 + 8 * i + 0]); g00 = fmaf(ha.x, wv.x, g00); g10 = fmaf(ha.x, wv.y, g10);
            wv = __half22float2(w2[64 + 8 * i + 1]); g01 = fmaf(ha.y, wv.x, g01); g11 = fmaf(ha.y, wv.y, g11);
            wv = __half22float2(w2[64 + 8 * i + 2]); g00 = fmaf(ha.z, wv.x, g00); g10 = fmaf(ha.z, wv.y, g10);
            wv = __half22float2(w2[64 + 8 * i + 3]); g01 = fmaf(ha.w, wv.x, g01); g11 = fmaf(ha.w, wv.y, g11);
            wv = __half22float2(w2[64 + 8 * i + 4]); g00 = fmaf(hb.x, wv.x, g00); g10 = fmaf(hb.x, wv.y, g10);
            wv = __half22float2(w2[64 + 8 * i + 5]); g01 = fmaf(hb.y, wv.x, g01); g11 = fmaf(hb.y, wv.y, g11);
            wv = __half22float2(w2[64 + 8 * i + 6]); g00 = fmaf(hb.z, wv.x, g00); g10 = fmaf(hb.z, wv.y, g10);
            wv = __half22float2(w2[64 + 8 * i + 7]); g01 = fmaf(hb.w, wv.x, g01); g11 = fmaf(hb.w, wv.y, g11);
        }
        const float ghSum0 = g00 + g01;
        const float ghSum1 = g10 + g11;
        const float sc0 = fminf((a0 + a1) + (a2 + a3), 80.0f);  // |sc|<~45; NaN safety
        const float sc1 = fminf((b0 + b1) + (b2 + b3), 80.0f);
        const float ev0 = __expf(sc0);                          // shift-invariant softmax
        const float ev1 = __expf(sc1);
        sE[tid] = ev0;
        sE[128 + tid] = ev1;
        __syncwarp();      // phase 2 consumes only this warp's own sE slices

        // ---- phase 2: context partials over this warp's 64 s values ----
        float2 c0a = {0.f, 0.f}, c1a = {0.f, 0.f}, c2a = {0.f, 0.f}, c3a = {0.f, 0.f};
#pragma unroll
        for (int i4 = 0; i4 < 8; i4++) {
            const float4 e4 = ev4[i4];                      // broadcast
            const float2 p0 = __half22float2(e2p[(i4 * 4 + 0) * 36]);
            const float2 p1 = __half22float2(e2p[(i4 * 4 + 1) * 36]);
            const float2 p2 = __half22float2(e2p[(i4 * 4 + 2) * 36]);
            const float2 p3 = __half22float2(e2p[(i4 * 4 + 3) * 36]);
            c0a.x = fmaf(e4.x, p0.x, c0a.x); c0a.y = fmaf(e4.x, p0.y, c0a.y);
            c1a.x = fmaf(e4.y, p1.x, c1a.x); c1a.y = fmaf(e4.y, p1.y, c1a.y);
            c2a.x = fmaf(e4.z, p2.x, c2a.x); c2a.y = fmaf(e4.z, p2.y, c2a.y);
            c3a.x = fmaf(e4.w, p3.x, c3a.x); c3a.y = fmaf(e4.w, p3.y, c3a.y);
        }
#pragma unroll
        for (int i4 = 0; i4 < 8; i4++) {
            const float4 e4 = ev4B[i4];                     // broadcast (s block +128)
            const float2 p0 = __half22float2(e2pB[(i4 * 4 + 0) * 36]);
            const float2 p1 = __half22float2(e2pB[(i4 * 4 + 1) * 36]);
            const float2 p2 = __half22float2(e2pB[(i4 * 4 + 2) * 36]);
            const float2 p3 = __half22float2(e2pB[(i4 * 4 + 3) * 36]);
            c0a.x = fmaf(e4.x, p0.x, c0a.x); c0a.y = fmaf(e4.x, p0.y, c0a.y);
            c1a.x = fmaf(e4.y, p1.x, c1a.x); c1a.y = fmaf(e4.y, p1.y, c1a.y);
            c2a.x = fmaf(e4.z, p2.x, c2a.x); c2a.y = fmaf(e4.z, p2.y, c2a.y);
            c3a.x = fmaf(e4.w, p3.x, c3a.x); c3a.y = fmaf(e4.w, p3.y, c3a.y);
        }
        float2 cp;
        cp.x = (c0a.x + c1a.x) + (c2a.x + c3a.x);
        cp.y = (c0a.y + c1a.y) + (c2a.y + c3a.y);
        ((float2*)sCpart)[(warp << 5) + lane] = cp;
        // softmax sum tree AFTER ph2 (overlaps ph2 LDS/FMA latency); result needed post-bar2
        float ss = ev0 + ev1;
#pragma unroll
        for (int o = 16; o > 0; o >>= 1) ss += __shfl_xor_sync(0xffffffffu, ss, o);
        if (lane == 0) sWsum[warp] = ss;
        __syncthreads();   // bar2

        // ---- phase 3: combine partials -> normalized context (tid<64) ----
        if (tid < 64) {
            const float cx = (sCpart[tid] + sCpart[64 + tid]) +
                             (sCpart[128 + tid] + sCpart[192 + tid]);
            const float sumE = (sWsum[0] + sWsum[1]) + (sWsum[2] + sWsum[3]);
            sCtx[tid] = cx * __fdividef(1.0f, sumE);
        }
        __syncthreads();   // bar3

        // ---- phase 4: gates ctx-part + inline cell via lane-pair shfl ----
        {
            float h00 = lg.x + ghSum0, h01 = 0.f;    // column j0
            float h10 = lg.y + ghSum1, h11 = 0.f;    // column j1
            const float4* xc4 = (const float4*)sCtx;
#pragma unroll
            for (int i = 0; i < 16; i++) {
                const float4 x4 = xc4[i];
                float2 wv;
                wv = __half22float2(w2[4 * i + 0]); h00 = fmaf(x4.x, wv.x, h00); h10 = fmaf(x4.x, wv.y, h10);
                wv = __half22float2(w2[4 * i + 1]); h01 = fmaf(x4.y, wv.x, h01); h11 = fmaf(x4.y, wv.y, h11);
                wv = __half22float2(w2[4 * i + 2]); h00 = fmaf(x4.z, wv.x, h00); h10 = fmaf(x4.z, wv.y, h10);
                wv = __half22float2(w2[4 * i + 3]); h01 = fmaf(x4.w, wv.x, h01); h11 = fmaf(x4.w, wv.y, h11);
            }
            const float gate0 = h00 + h01;   // even: i_hh, odd: f_hh
            const float gate1 = h10 + h11;   // even: g_hh, odd: o_hh
            const float oth0 = __shfl_xor_sync(0xffffffffu, gate0, 1);
            const float oth1 = __shfl_xor_sync(0xffffffffu, gate1, 1);
            if ((tid & 1) == 0) {
                const float gi = gate0, gf = oth0, gg = gate1, go = oth1;
                const float cn = sigf(gf) * sCst[hh] + sigf(gi) * tanhfast(gg);
                const float hn = sigf(go) * tanhfast(cn);
                sCst[hh] = cn;
                hN[hh] = hn;      // ping-pong: no race with hP readers
            }
        }
        __syncthreads();   // bar4 (cell results visible)

        // ---- phase 5: logits partials, warp <-> 32-k chunk, lane <-> v ----
        {
            const int k0 = warp << 5;
            const float4* x4p = (warp < 2) ? (const float4*)(sCtx + k0)
                                           : (const float4*)(hN + (k0 - 64));
            float lp0 = 0.f, lp1 = 0.f;
#pragma unroll
            for (int i = 0; i < 8; i++) {
                const float4 x4 = x4p[i];
                const float* fp = sFcP + (k0 + 4 * i) * 32 + lane;
                lp0 = fmaf(x4.x, fp[0],  lp0);
                lp1 = fmaf(x4.y, fp[32], lp1);
                lp0 = fmaf(x4.z, fp[64], lp0);
                lp1 = fmaf(x4.w, fp[96], lp1);
            }
            sLpart[(warp << 5) + lane] = lp0 + lp1;
        }
        __syncthreads();   // bar5

        // ---- phase 6: final reduce + store (warp 0) ----
        if (warp == 0 && lane < NV) {
            const float acc = sFcb[lane] +
                ((sLpart[lane] + sLpart[32 + lane]) + (sLpart[64 + lane] + sLpart[96 + lane]));
            out[((size_t)b * NT + t) * NV + lane] = acc;
        }
        // hazards: sE is warp-private (ph1 writes, ph2 same-warp reads) -> no cross-step bar;
        // next ph2 writes sCpart after this ph3 reads (bar3, bar4, bar5 between);
        // next ph5 writes sLpart after this ph6 reads (bar2..bar4 between);
        // next ph3 writes sCtx after this ph5 reads (bar5 + next bar2 between);
        // cell writes hN, readers of hP unaffected (ping-pong)
    }
}

extern "C" void kernel_launch(void* const* d_in, const int* in_sizes, int n_in,
                              void* d_out, int out_size) {
    const int*   y      = (const int*)d_in[0];
    const float* h0     = (const float*)d_in[1];
    const float* c0     = (const float*)d_in[2];
    const float* encout = (const float*)d_in[3];
    const float* emb    = (const float*)d_in[4];
    const float* W_ih   = (const float*)d_in[5];
    const float* W_hh   = (const float*)d_in[6];
    const float* b_ih   = (const float*)d_in[7];
    const float* b_hh   = (const float*)d_in[8];
    const float* fc_W   = (const float*)d_in[9];
    const float* fc_b   = (const float*)d_in[10];
    float* out = (float*)d_out;

    cudaFuncSetAttribute(decoder_kernel, cudaFuncAttributeMaxDynamicSharedMemorySize, SMEM_BYTES);

    setup_kernel<<<NV + 2, 128>>>(emb, W_ih, W_hh, b_ih, b_hh, fc_W, fc_b);
    decoder_kernel<<<NB, 128, SMEM_BYTES>>>(y, h0, c0, encout, out);
}

// round 16
// speedup vs baseline: 1.0051x; 1.0051x over previous
#include <cuda_runtime.h>
#include <cuda_fp16.h>

#define NB 2048
#define NT 128
#define NS 256
#define NH 64
#define NE 32
#define NV 29

// ---------------- precomputed constants (filled by setup_kernel) ----------------
// thread t (0..127): hh = t>>1, c = t&1; gate columns j0 = hh + 64c, j1 = 128 + hh + 64c.
// (even lane: i_hh and g_hh; odd lane: f_hh and o_hh)
__device__ __half2 g_wTh[128 * 128];  // [k][t] = half2(W[k][j0], W[k][j1]); k<64: W_ih ctx, k>=64: W_hh
__device__ float2  g_lut2[NV * 128];  // [v][t] = (lut[v][j0], lut[v][j1])
__device__ float   g_fcP[128 * 32];   // [k][v]: xc order [context(0..63), h_new(64..127)]; v>=29 -> 0
__device__ float   g_fcb[32];

__device__ __forceinline__ float sigf(float x) {
    return __fdividef(1.0f, 1.0f + __expf(-x));
}
__device__ __forceinline__ float tanhfast(float x) {
    return 1.0f - __fdividef(2.0f, __expf(2.0f * x) + 1.0f);
}

__global__ void setup_kernel(const float* __restrict__ emb, const float* __restrict__ W_ih,
                             const float* __restrict__ W_hh, const float* __restrict__ b_ih,
                             const float* __restrict__ b_hh, const float* __restrict__ fc_W,
                             const float* __restrict__ fc_b) {
    const int t = threadIdx.x;     // 0..127
    const int blk = blockIdx.x;
    const int hh = t >> 1, c = t & 1;
    const int j0 = hh + 64 * c;
    const int j1 = 128 + hh + 64 * c;
    if (blk < NV) {
        float s[2];
        const int js[2] = { j0, j1 };
#pragma unroll
        for (int q = 0; q < 2; q++) {
            const int j = js[q];
            float acc = b_ih[j] + b_hh[j];
#pragma unroll
            for (int e = 0; e < NE; e++) acc += emb[blk * NE + e] * W_ih[j * (NE + NH) + e];
            s[q] = acc;
        }
        g_lut2[blk * 128 + t] = make_float2(s[0], s[1]);
    } else if (blk == NV) {
        for (int k = 0; k < 128; k++) {
            float w0, w1;
            if (k < 64) {
                w0 = W_ih[j0 * (NE + NH) + NE + k];
                w1 = W_ih[j1 * (NE + NH) + NE + k];
            } else {
                w0 = W_hh[j0 * NH + (k - 64)];
                w1 = W_hh[j1 * NH + (k - 64)];
            }
            g_wTh[k * 128 + t] = __floats2half2_rn(w0, w1);
        }
    } else {
        for (int idx = t; idx < 4096; idx += 128) {
            const int k = idx >> 5, v = idx & 31;
            float val = 0.0f;
            if (v < NV) val = (k < 64) ? fc_W[v * 128 + 64 + k] : fc_W[v * 128 + (k - 64)];
            g_fcP[idx] = val;
        }
        if (t < 32) g_fcb[t] = (t < NV) ? fc_b[t] : 0.0f;
    }
}

// ---------------- smem layout (offsets in floats), 1 row per CTA, 128 threads ----------------
#define OFF_ENC16  0        // 256*72 halves = 9216 floats
#define OFF_FCP    9216     // 4096
#define OFF_CTX    13312    // 64
#define OFF_HBUF   13376    // 2 * 64 (h ping-pong)
#define OFF_CST    13504    // 64
#define OFF_E      13568    // 256  softmax weights (warp-private)
#define OFF_CPART  13824    // 256
#define OFF_LPART  14080    // 128
#define OFF_WSUM   14208    // 8 (4 used)
#define OFF_FCB    14216    // 32
#define OFF_Y      14248    // 128 ints
#define SMEM_FLOATS 14376
#define SMEM_BYTES (SMEM_FLOATS * 4)   // 57504 -> 2 CTAs/SM = 115 KB

__global__ void __launch_bounds__(128, 2)
decoder_kernel(const int* __restrict__ y, const float* __restrict__ h0,
               const float* __restrict__ c0, const float* __restrict__ enc,
               float* __restrict__ out) {
    extern __shared__ float sm[];
    __half*  sEnc16 = (__half*)(sm + OFF_ENC16);
    float*   sFcP   = sm + OFF_FCP;
    float*   sCtx   = sm + OFF_CTX;
    float*   sHbuf  = sm + OFF_HBUF;
    float*   sCst   = sm + OFF_CST;
    float*   sE     = sm + OFF_E;
    float*   sCpart = sm + OFF_CPART;
    float*   sLpart = sm + OFF_LPART;
    float*   sWsum  = sm + OFF_WSUM;
    float*   sFcb   = sm + OFF_FCB;
    int*     sY     = (int*)(sm + OFF_Y);

    const int b = blockIdx.x, tid = threadIdx.x;   // 128 threads
    const int lane = tid & 31, warp = tid >> 5;    // 4 warps

    // one-time loads
    const float* encb = enc + (size_t)b * (NS * NH);
    for (int idx = tid; idx < NS * NH; idx += 128) {
        const int s = idx >> 6, h = idx & 63;
        sEnc16[s * 72 + h] = __float2half(encb[idx]);
    }
    for (int idx = tid; idx < 4096; idx += 128) sFcP[idx] = g_fcP[idx];
    if (tid < 64) { sHbuf[tid] = h0[b * 64 + tid]; sCst[tid] = c0[b * 64 + tid]; }
    sY[tid] = y[b * 128 + tid];
    if (tid < 32) sFcb[tid] = g_fcb[tid];

    // per-thread packed gate weights for columns (j0, j1)
    __half2 w2[128];
#pragma unroll
    for (int k = 0; k < 128; k++) w2[k] = g_wTh[k * 128 + tid];
    __syncthreads();

    // scores: thread owns encoder rows s = tid and s = tid+128
    const uint4* er0 = (const uint4*)(sEnc16 + tid * 72);
    const uint4* er1 = er0 + 1152;                 // +128 rows * 72 halves
    // context: warp w <-> s blocks [32w,32w+32) and [128+32w,...), lane <-> h-pair
    const __half2* e2p  = (const __half2*)sEnc16 + warp * (32 * 36) + lane;
    const __half2* e2pB = e2p + 128 * 36;
    const float4*  ev4  = (const float4*)(sE + (warp << 5));
    const float4*  ev4B = (const float4*)(sE + 128 + (warp << 5));
    const int hh = tid >> 1;

    for (int t = 0; t < NT; t++) {
        const float* hP = sHbuf + (t & 1) * 64;        // h for this step
        float*       hN = sHbuf + ((t + 1) & 1) * 64;  // h_new written here
        const float2 lg = g_lut2[sY[t] * 128 + tid];   // L2 load; consumed in phase 4

        // ---- phase 1: fp16 scores (2 rows) + exp + gates_h (both cols) ----
        const float4* hv4 = (const float4*)hP;
        float a0 = 0.f, a1 = 0.f, a2 = 0.f, a3 = 0.f;
        float b0 = 0.f, b1 = 0.f, b2 = 0.f, b3 = 0.f;
        float g00 = 0.f, g01 = 0.f, g10 = 0.f, g11 = 0.f;
#pragma unroll
        for (int i = 0; i < 8; i++) {
            const uint4 u0 = er0[i];
            const uint4 u1 = er1[i];
            const float4 ha = hv4[2 * i], hb = hv4[2 * i + 1];
            float2 e;
            e = __half22float2(*(const __half2*)&u0.x); a0 = fmaf(e.x, ha.x, a0); a1 = fmaf(e.y, ha.y, a1);
            e = __half22float2(*(const __half2*)&u0.y); a2 = fmaf(e.x, ha.z, a2); a3 = fmaf(e.y, ha.w, a3);
            e = __half22float2(*(const __half2*)&u0.z); a0 = fmaf(e.x, hb.x, a0); a1 = fmaf(e.y, hb.y, a1);
            e = __half22float2(*(const __half2*)&u0.w); a2 = fmaf(e.x, hb.z, a2); a3 = fmaf(e.y, hb.w, a3);
            e = __half22float2(*(const __half2*)&u1.x); b0 = fmaf(e.x, ha.x, b0); b1 = fmaf(e.y, ha.y, b1);
            e = __half22float2(*(const __half2*)&u1.y); b2 = fmaf(e.x, ha.z, b2); b3 = fmaf(e.y, ha.w, b3);
            e = __half22float2(*(const __half2*)&u1.z); b0 = fmaf(e.x, hb.x, b0); b1 = fmaf(e.y, hb.y, b1);
            e = __half22float2(*(const __half2*)&u1.w); b2 = fmaf(e.x, hb.z, b2); b3 = fmaf(e.y, hb.w, b3);
            float2 wv;
            wv = __half22float2(w2[64 + 8 * i + 0]); g00 = fmaf(ha.x, wv.x, g00); g10 = fmaf(ha.x, wv.y, g10);
            wv = __half22float2(w2[64 + 8 * i + 1]); g01 = fmaf(ha.y, wv.x, g01); g11 = fmaf(ha.y, wv.y, g11);
            wv = __half22float2(w2[64 + 8 * i + 2]); g00 = fmaf(ha.z, wv.x, g00); g10 = fmaf(ha.z, wv.y, g10);
            wv = __half22float2(w2[64 + 8 * i + 3]); g01 = fmaf(ha.w, wv.x, g01); g11 = fmaf(ha.w, wv.y, g11);
            wv = __half22float2(w2[64 + 8 * i + 4]); g00 = fmaf(hb.x, wv.x, g00); g10 = fmaf(hb.x, wv.y, g10);
            wv = __half22float2(w2[64 + 8 * i + 5]); g01 = fmaf(hb.y, wv.x, g01); g11 = fmaf(hb.y, wv.y, g11);
            wv = __half22float2(w2[64 + 8 * i + 6]); g00 = fmaf(hb.z, wv.x, g00); g10 = fmaf(hb.z, wv.y, g10);
            wv = __half22float2(w2[64 + 8 * i + 7]); g01 = fmaf(hb.w, wv.x, g01); g11 = fmaf(hb.w, wv.y, g11);
        }
        const float ghSum0 = g00 + g01;
        const float ghSum1 = g10 + g11;
        const float sc0 = fminf((a0 + a1) + (a2 + a3), 80.0f);  // |sc|<~45; NaN safety
        const float sc1 = fminf((b0 + b1) + (b2 + b3), 80.0f);
        const float ev0 = __expf(sc0);                          // shift-invariant softmax
        const float ev1 = __expf(sc1);
        sE[tid] = ev0;
        sE[128 + tid] = ev1;
        __syncwarp();      // phase 2 consumes only this warp's own sE slices

        // ---- phase 2: context partials over this warp's 64 s values ----
        float2 c0a = {0.f, 0.f}, c1a = {0.f, 0.f}, c2a = {0.f, 0.f}, c3a = {0.f, 0.f};
#pragma unroll
        for (int i4 = 0; i4 < 8; i4++) {
            const float4 e4 = ev4[i4];                      // broadcast
            const float2 p0 = __half22float2(e2p[(i4 * 4 + 0) * 36]);
            const float2 p1 = __half22float2(e2p[(i4 * 4 + 1) * 36]);
            const float2 p2 = __half22float2(e2p[(i4 * 4 + 2) * 36]);
            const float2 p3 = __half22float2(e2p[(i4 * 4 + 3) * 36]);
            c0a.x = fmaf(e4.x, p0.x, c0a.x); c0a.y = fmaf(e4.x, p0.y, c0a.y);
            c1a.x = fmaf(e4.y, p1.x, c1a.x); c1a.y = fmaf(e4.y, p1.y, c1a.y);
            c2a.x = fmaf(e4.z, p2.x, c2a.x); c2a.y = fmaf(e4.z, p2.y, c2a.y);
            c3a.x = fmaf(e4.w, p3.x, c3a.x); c3a.y = fmaf(e4.w, p3.y, c3a.y);
        }
#pragma unroll
        for (int i4 = 0; i4 < 8; i4++) {
            const float4 e4 = ev4B[i4];                     // broadcast (s block +128)
            const float2 p0 = __half22float2(e2pB[(i4 * 4 + 0) * 36]);
            const float2 p1 = __half22float2(e2pB[(i4 * 4 + 1) * 36]);
            const float2 p2 = __half22float2(e2pB[(i4 * 4 + 2) * 36]);
            const float2 p3 = __half22float2(e2pB[(i4 * 4 + 3) * 36]);
            c0a.x = fmaf(e4.x, p0.x, c0a.x); c0a.y = fmaf(e4.x, p0.y, c0a.y);
            c1a.x = fmaf(e4.y, p1.x, c1a.x); c1a.y = fmaf(e4.y, p1.y, c1a.y);
            c2a.x = fmaf(e4.z, p2.x, c2a.x); c2a.y = fmaf(e4.z, p2.y, c2a.y);
            c3a.x = fmaf(e4.w, p3.x, c3a.x); c3a.y = fmaf(e4.w, p3.y, c3a.y);
        }
        float2 cp;
        cp.x = (c0a.x + c1a.x) + (c2a.x + c3a.x);
        cp.y = (c0a.y + c1a.y) + (c2a.y + c3a.y);
        ((float2*)sCpart)[(warp << 5) + lane] = cp;
        // softmax sum tree AFTER ph2 (overlaps ph2 LDS/FMA latency); result needed post-bar2
        float ss = ev0 + ev1;
#pragma unroll
        for (int o = 16; o > 0; o >>= 1) ss += __shfl_xor_sync(0xffffffffu, ss, o);
        if (lane == 0) sWsum[warp] = ss;
        __syncthreads();   // bar2

        // ---- phase 3: combine partials -> normalized context (tid<64) ----
        if (tid < 64) {
            const float cx = (sCpart[tid] + sCpart[64 + tid]) +
                             (sCpart[128 + tid] + sCpart[192 + tid]);
            const float sumE = (sWsum[0] + sWsum[1]) + (sWsum[2] + sWsum[3]);
            sCtx[tid] = cx * __fdividef(1.0f, sumE);
        }
        __syncthreads();   // bar3

        // ---- phase 4: gates ctx-part + inline cell via lane-pair shfl ----
        {
            float h00 = lg.x + ghSum0, h01 = 0.f;    // column j0
            float h10 = lg.y + ghSum1, h11 = 0.f;    // column j1
            const float4* xc4 = (const float4*)sCtx;
#pragma unroll
            for (int i = 0; i < 16; i++) {
                const float4 x4 = xc4[i];
                float2 wv;
                wv = __half22float2(w2[4 * i + 0]); h00 = fmaf(x4.x, wv.x, h00); h10 = fmaf(x4.x, wv.y, h10);
                wv = __half22float2(w2[4 * i + 1]); h01 = fmaf(x4.y, wv.x, h01); h11 = fmaf(x4.y, wv.y, h11);
                wv = __half22float2(w2[4 * i + 2]); h00 = fmaf(x4.z, wv.x, h00); h10 = fmaf(x4.z, wv.y, h10);
                wv = __half22float2(w2[4 * i + 3]); h01 = fmaf(x4.w, wv.x, h01); h11 = fmaf(x4.w, wv.y, h11);
            }
            const float gate0 = h00 + h01;   // even: i_hh, odd: f_hh
            const float gate1 = h10 + h11;   // even: g_hh, odd: o_hh
            const float oth0 = __shfl_xor_sync(0xffffffffu, gate0, 1);
            const float oth1 = __shfl_xor_sync(0xffffffffu, gate1, 1);
            if ((tid & 1) == 0) {
                const float gi = gate0, gf = oth0, gg = gate1, go = oth1;
                const float cn = sigf(gf) * sCst[hh] + sigf(gi) * tanhfast(gg);
                const float hn = sigf(go) * tanhfast(cn);
                sCst[hh] = cn;
                hN[hh] = hn;      // ping-pong: no race with hP readers
            }
        }
        __syncthreads();   // bar4 (cell results visible)

        // ---- phase 5: logits partials, warp <-> 32-k chunk, lane <-> v ----
        {
            const int k0 = warp << 5;
            const float4* x4p = (warp < 2) ? (const float4*)(sCtx + k0)
                                           : (const float4*)(hN + (k0 - 64));
            float lp0 = 0.f, lp1 = 0.f;
#pragma unroll
            for (int i = 0; i < 8; i++) {
                const float4 x4 = x4p[i];
                const float* fp = sFcP + (k0 + 4 * i) * 32 + lane;
                lp0 = fmaf(x4.x, fp[0],  lp0);
                lp1 = fmaf(x4.y, fp[32], lp1);
                lp0 = fmaf(x4.z, fp[64], lp0);
                lp1 = fmaf(x4.w, fp[96], lp1);
            }
            sLpart[(warp << 5) + lane] = lp0 + lp1;
        }
        __syncthreads();   // bar5

        // ---- phase 6: final reduce + store (warp 0) ----
        if (warp == 0 && lane < NV) {
            const float acc = sFcb[lane] +
                ((sLpart[lane] + sLpart[32 + lane]) + (sLpart[64 + lane] + sLpart[96 + lane]));
            out[((size_t)b * NT + t) * NV + lane] = acc;
        }
        // hazards: sE is warp-private (ph1 writes, ph2 same-warp reads) -> no cross-step bar;
        // next ph2 writes sCpart after this ph3 reads (bar3, bar4, bar5 between);
        // next ph5 writes sLpart after this ph6 reads (bar2..bar4 between);
        // next ph3 writes sCtx after this ph5 reads (bar5 + next bar2 between);
        // cell writes hN, readers of hP unaffected (ping-pong)
    }
}

extern "C" void kernel_launch(void* const* d_in, const int* in_sizes, int n_in,
                              void* d_out, int out_size) {
    const int*   y      = (const int*)d_in[0];
    const float* h0     = (const float*)d_in[1];
    const float* c0     = (const float*)d_in[2];
    const float* encout = (const float*)d_in[3];
    const float* emb    = (const float*)d_in[4];
    const float* W_ih   = (const float*)d_in[5];
    const float* W_hh   = (const float*)d_in[6];
    const float* b_ih   = (const float*)d_in[7];
    const float* b_hh   = (const float*)d_in[8];
    const float* fc_W   = (const float*)d_in[9];
    const float* fc_b   = (const float*)d_in[10];
    float* out = (float*)d_out;

    cudaFuncSetAttribute(decoder_kernel, cudaFuncAttributeMaxDynamicSharedMemorySize, SMEM_BYTES);

    setup_kernel<<<NV + 2, 128>>>(emb, W_ih, W_hh, b_ih, b_hh, fc_W, fc_b);
    decoder_kernel<<<NB, 128, SMEM_BYTES>>>(y, h0, c0, encout, out);
}